// round 5
// baseline (speedup 1.0000x reference)
#include <cuda_runtime.h>
#include <cuda_bf16.h>
#include <cmath>

// SimpleHashEncoder1D: out[p, l*2 + f] = hash_table[floor((x[p]+1)/2 * scale_l + 0.5) % T, f]
//
// Numerics (LOCKED, rel_err=0.0 since R2 — do not change):
//   b = f32 1 ulp below 2.0f; scale_l = f32(16 * f32(b^l)) - 1.0f via double pow;
//   x_scaled = xn*scale + 0.5 with SEPARATE roundings (no FMA).
//
// R5: revert R4's smem/persistent experiment (regressed: LDS bank conflicts cost the
// same l1tex cycles, and 3 CTAs/SM cut occupancy). Back to R3 structure (80.4us),
// plus cache-policy split: levels >= 10 (footprint 128KB..4MB) load with __ldcg
// (L2-only, no L1 allocate) so levels 0..9 (131KB) stay fully L1-resident.

#define T_SIZE   524288      // 2^19
#define N_POINTS (1 << 21)   // 2097152
#define NUM_L    16
#define PTS_PER_THREAD 4
#define P_QUARTER (N_POINTS / PTS_PER_THREAD)   // 524288

struct Scales { float s[NUM_L]; };

__global__ __launch_bounds__(256)
void hashenc_kernel(const float* __restrict__ x,
                    const float2* __restrict__ table,
                    float4* __restrict__ out,
                    const Scales sc)
{
    int gid = blockIdx.x * blockDim.x + threadIdx.x;   // 4M threads
    int j  = gid & 7;          // level-pair index 0..7 (levels 2j, 2j+1)
    int p0 = gid >> 3;         // base point in [0, 512K)

    int l0 = j << 1;
    float s0 = sc.s[l0];
    float s1 = sc.s[l0 + 1];

    // Batch the 4 independent x-loads (lanes 0-7 share p0 -> broadcast line)
    float xv[PTS_PER_THREAD];
#pragma unroll
    for (int k = 0; k < PTS_PER_THREAD; k++)
        xv[k] = __ldg(&x[p0 + k * P_QUARTER]);

    // Indices: xn = (x+1)*0.5 ; v = xn*s + 0.5, separate roundings (no FMA)
    int i0[PTS_PER_THREAD], i1[PTS_PER_THREAD];
#pragma unroll
    for (int k = 0; k < PTS_PER_THREAD; k++) {
        float xn = __fmul_rn(__fadd_rn(xv[k], 1.0f), 0.5f);
        float v0 = __fadd_rn(__fmul_rn(xn, s0), 0.5f);
        float v1 = __fadd_rn(__fmul_rn(xn, s1), 0.5f);
        i0[k] = ((int)v0) & (T_SIZE - 1);   // v >= 0.5 -> trunc == floor
        i1[k] = ((int)v1) & (T_SIZE - 1);
    }

    // Batch all 8 independent gathers.
    // j >= 5 -> levels 10..15: stream via L2 only (__ldcg), keep L1 for levels 0..9.
    float2 f0[PTS_PER_THREAD], f1[PTS_PER_THREAD];
    if (j >= 5) {
#pragma unroll
        for (int k = 0; k < PTS_PER_THREAD; k++) {
            f0[k] = __ldcg(&table[i0[k]]);
            f1[k] = __ldcg(&table[i1[k]]);
        }
    } else {
#pragma unroll
        for (int k = 0; k < PTS_PER_THREAD; k++) {
            f0[k] = __ldg(&table[i0[k]]);
            f1[k] = __ldg(&table[i1[k]]);
        }
    }

    // 4 perfectly coalesced float4 store streams: out index = point*8 + j
#pragma unroll
    for (int k = 0; k < PTS_PER_THREAD; k++) {
        int oi = ((p0 + k * P_QUARTER) << 3) + j;
        out[oi] = make_float4(f0[k].x, f0[k].y, f1[k].x, f1[k].y);
    }
}

extern "C" void kernel_launch(void* const* d_in, const int* in_sizes, int n_in,
                              void* d_out, int out_size)
{
    const float*  x     = (const float*)d_in[0];
    const float2* table = (const float2*)d_in[1];
    // d_in[2] is `bound` (== 1): folded into the normalize.
    float4* out = (float4*)d_out;

    // b = f32 value 1 ulp below 2.0f (0x3FFFFFFF)
    const float b = 1.99999988079071044921875f;
    Scales sc;
    for (int l = 0; l < NUM_L; l++) {
        double pd = pow((double)b, (double)l);   // correctly rounded double
        float  pf = (float)pd;                   // == f32 pow result
        float  q  = 16.0f * pf;                  // exact
        sc.s[l]   = q - 1.0f;                    // f32 rounding
    }

    int total_threads = (N_POINTS / PTS_PER_THREAD) * (NUM_L / 2);  // 4M
    int block = 256;
    int grid  = total_threads / block;                              // 16384
    hashenc_kernel<<<grid, block>>>(x, table, out, sc);
}

// round 6
// speedup vs baseline: 1.1812x; 1.1812x over previous
#include <cuda_runtime.h>
#include <cuda_bf16.h>
#include <cmath>

// SimpleHashEncoder1D: out[p, l*2 + f] = hash_table[floor((x[p]+1)/2 * scale_l + 0.5) % T, f]
//
// Numerics (LOCKED, rel_err=0.0 since R2 — do not change):
//   b = f32 1 ulp below 2.0f; scale_l = f32(16 * f32(b^l)) - 1.0f via double pow;
//   x_scaled = xn*scale + 0.5 with SEPARATE roundings (no FMA).
//
// R6: revert R5's __ldcg (regressed — all loads consume l1tex wavefronts regardless
// of cache policy). R3 structure, PTS_PER_THREAD 4 -> 8: 16 independent batched
// gathers per thread to saturate the l1tex wavefront queue (~1 wf/cyc/SM is the
// hard floor; R3 ran it at 81%).

#define T_SIZE   524288      // 2^19
#define N_POINTS (1 << 21)   // 2097152
#define NUM_L    16
#define PTS_PER_THREAD 8
#define P_SLICE (N_POINTS / PTS_PER_THREAD)   // 262144

struct Scales { float s[NUM_L]; };

__global__ __launch_bounds__(256)
void hashenc_kernel(const float* __restrict__ x,
                    const float2* __restrict__ table,
                    float4* __restrict__ out,
                    const Scales sc)
{
    int gid = blockIdx.x * blockDim.x + threadIdx.x;   // 2M threads
    int j  = gid & 7;          // level-pair index 0..7 (levels 2j, 2j+1)
    int p0 = gid >> 3;         // base point in [0, 256K)

    int l0 = j << 1;
    float s0 = sc.s[l0];
    float s1 = sc.s[l0 + 1];

    // Batch the 8 independent x-loads (lanes 0-7 share each p -> broadcast lines)
    float xv[PTS_PER_THREAD];
#pragma unroll
    for (int k = 0; k < PTS_PER_THREAD; k++)
        xv[k] = __ldg(&x[p0 + k * P_SLICE]);

    // Indices: xn = (x+1)*0.5 ; v = xn*s + 0.5, separate roundings (no FMA)
    int i0[PTS_PER_THREAD], i1[PTS_PER_THREAD];
#pragma unroll
    for (int k = 0; k < PTS_PER_THREAD; k++) {
        float xn = __fmul_rn(__fadd_rn(xv[k], 1.0f), 0.5f);
        float v0 = __fadd_rn(__fmul_rn(xn, s0), 0.5f);
        float v1 = __fadd_rn(__fmul_rn(xn, s1), 0.5f);
        i0[k] = ((int)v0) & (T_SIZE - 1);   // v >= 0.5 -> trunc == floor
        i1[k] = ((int)v1) & (T_SIZE - 1);
    }

    // Batch all 16 independent gathers -> deep MLP against the l1tex queue
    float2 f0[PTS_PER_THREAD], f1[PTS_PER_THREAD];
#pragma unroll
    for (int k = 0; k < PTS_PER_THREAD; k++) {
        f0[k] = __ldg(&table[i0[k]]);
        f1[k] = __ldg(&table[i1[k]]);
    }

    // 8 perfectly coalesced float4 store streams: out index = point*8 + j
#pragma unroll
    for (int k = 0; k < PTS_PER_THREAD; k++) {
        int oi = ((p0 + k * P_SLICE) << 3) + j;
        out[oi] = make_float4(f0[k].x, f0[k].y, f1[k].x, f1[k].y);
    }
}

extern "C" void kernel_launch(void* const* d_in, const int* in_sizes, int n_in,
                              void* d_out, int out_size)
{
    const float*  x     = (const float*)d_in[0];
    const float2* table = (const float2*)d_in[1];
    // d_in[2] is `bound` (== 1): folded into the normalize.
    float4* out = (float4*)d_out;

    // b = f32 value 1 ulp below 2.0f (0x3FFFFFFF)
    const float b = 1.99999988079071044921875f;
    Scales sc;
    for (int l = 0; l < NUM_L; l++) {
        double pd = pow((double)b, (double)l);   // correctly rounded double
        float  pf = (float)pd;                   // == f32 pow result
        float  q  = 16.0f * pf;                  // exact
        sc.s[l]   = q - 1.0f;                    // f32 rounding
    }

    int total_threads = (N_POINTS / PTS_PER_THREAD) * (NUM_L / 2);  // 2M
    int block = 256;
    int grid  = total_threads / block;                              // 8192
    hashenc_kernel<<<grid, block>>>(x, table, out, sc);
}